// round 14
// baseline (speedup 1.0000x reference)
#include <cuda_runtime.h>
#include <cuda_fp16.h>
#include <math.h>

// ---------------------------------------------------------------------------
// B=8, N=2048, C=1024, heads=2, d=512, H=2048.  M = B*N = 16384.
// GEMMs: fp16 in (A[m][k], B[n][k]), fp32 accum, mma.sync m16n8k16,
// 4-stage cp.async, CTA tile 128x128 with 512 threads / warp tile 32x32
// (acc 32 regs/thread -> ~64 total -> 32 warps/SM, 2x occupancy vs the
// 256-thread/64x32 variant). Softmax fused into epilogues; V transpose
// fused into QKV; weight transposes overlap LN1 via stream fork.
// ---------------------------------------------------------------------------

#define BM 128
#define BN 128
#define BK 32
#define ASTR 40                        // padded smem row stride (80B)
#define NSTAGE 4
#define STG_HALFS (2 * 128 * ASTR)     // A + B per stage (20KB)
#define SMEM_BYTES (NSTAGE * STG_HALFS * 2)
#define PADH 136                       // V-transpose stage row stride (halfs)

enum { EPI_NONE = 0, EPI_BIAS = 1, EPI_BIAS_RES = 2, EPI_BIAS_GELU = 3,
       EPI_EXP = 4, EPI_DIVROW = 5, EPI_QKV = 6 };

// ---------------- scratch (device globals, allocation-free) ----------------
__device__ __half g_xn[16384 * 1024];
__device__ __half g_qkv[16384 * 3072];
__device__ __half g_vT[16ull * 512 * 2048];
__device__ __half g_scores[16ull * 2048 * 2048];
__device__ __half g_attnout[16384 * 1024];
__device__ float  g_x1[16384 * 1024];
__device__ __half g_hdn[16384 * 2048];
__device__ __half g_qkvwT[3072 * 1024];
__device__ __half g_projwT[1024 * 1024];
__device__ __half g_w1T[2048 * 1024];
__device__ __half g_w2T[1024 * 2048];
__device__ float  g_partials[16 * 16 * 2048];   // [z][ntile][row]
__device__ float  g_rowsum[16 * 2048];

__device__ __forceinline__ void cpa16(__half* dst, const __half* src) {
    unsigned d = (unsigned)__cvta_generic_to_shared(dst);
    asm volatile("cp.async.cg.shared.global [%0], [%1], 16;" :: "r"(d), "l"(src));
}

__device__ __forceinline__ void mma_f16(float c[4], const unsigned a[4], const unsigned b[2]) {
    asm volatile(
        "mma.sync.aligned.m16n8k16.row.col.f32.f16.f16.f32 "
        "{%0,%1,%2,%3}, {%4,%5,%6,%7}, {%8,%9}, {%0,%1,%2,%3};"
        : "+f"(c[0]), "+f"(c[1]), "+f"(c[2]), "+f"(c[3])
        : "r"(a[0]), "r"(a[1]), "r"(a[2]), "r"(a[3]), "r"(b[0]), "r"(b[1]));
}

// ---------------------------------------------------------------------------
// fp16 tensor-core GEMM: C[z] = A[z] @ B[z]^T + epilogue.
// A: [M][K] ld=lda, B: [N][K] ld=ldb. K % 32 == 0, K/32 >= 3.
// 512 threads; warp grid 4m x 4n; warp tile 32x32.
// ---------------------------------------------------------------------------
template <int EPI, typename OutT>
__global__ __launch_bounds__(512, 2) void gemm_h(
    const __half* __restrict__ A, const __half* __restrict__ B,
    const float* __restrict__ bias, const float* __restrict__ resid,
    const float* __restrict__ rsum, float* __restrict__ parts,
    __half* __restrict__ vTp, float escale,
    OutT* __restrict__ C,
    int K, int lda, int ldb, int ldc,
    long long soA, long long siA,
    long long soB, long long siB,
    long long soC, long long siC, int ic)
{
    extern __shared__ __half smem[];

    const int z = blockIdx.z;
    A += (long long)(z / ic) * soA + (long long)(z % ic) * siA;
    B += (long long)(z / ic) * soB + (long long)(z % ic) * siB;
    C += (long long)(z / ic) * soC + (long long)(z % ic) * siC;
    if (EPI == EPI_DIVROW) rsum += (long long)z * 2048;

    const int m0 = blockIdx.y * BM;
    const int n0 = blockIdx.x * BN;
    const int tid = threadIdx.x;
    const int lane = tid & 31;
    const int warp = tid >> 5;          // 0..15
    const int wm = (warp & 3) * 32;     // 0,32,64,96
    const int wn = (warp >> 2) * 32;    // 0,32,64,96
    const int lq = lane >> 2;
    const int lr = lane & 3;

    float acc[2][4][4];
#pragma unroll
    for (int i = 0; i < 2; i++)
#pragma unroll
        for (int j = 0; j < 4; j++)
#pragma unroll
            for (int c = 0; c < 4; c++) acc[i][j][c] = 0.0f;

    const int ldr = tid >> 2;           // 0..127 (one row each)
    const int ldc4 = (tid & 3) * 8;     // 16B chunk in 32-half row

    auto load_tile = [&](int t, int s) {
        __half* sA = smem + s * STG_HALFS;
        __half* sB = sA + 128 * ASTR;
        const __half* gA = A + (size_t)(m0 + ldr) * lda + t * BK + ldc4;
        const __half* gB = B + (size_t)(n0 + ldr) * ldb + t * BK + ldc4;
        cpa16(sA + ldr * ASTR + ldc4, gA);
        cpa16(sB + ldr * ASTR + ldc4, gB);
    };

    const int ntiles = K / BK;
    load_tile(0, 0);
    asm volatile("cp.async.commit_group;");
    load_tile(1, 1);
    asm volatile("cp.async.commit_group;");
    load_tile(2, 2);
    asm volatile("cp.async.commit_group;");

    for (int t = 0; t < ntiles; t++) {
        const int p = t & (NSTAGE - 1);
        asm volatile("cp.async.wait_group 2;");
        __syncthreads();

        const __half* sA = smem + p * STG_HALFS;
        const __half* sB = sA + 128 * ASTR;
#pragma unroll
        for (int kk = 0; kk < BK; kk += 16) {
            unsigned a[2][4], b[4][2];
#pragma unroll
            for (int mi = 0; mi < 2; mi++) {
                const __half* pa = sA + (wm + mi * 16 + lq) * ASTR + kk + lr * 2;
                a[mi][0] = *(const unsigned*)pa;
                a[mi][1] = *(const unsigned*)(pa + 8 * ASTR);
                a[mi][2] = *(const unsigned*)(pa + 8);
                a[mi][3] = *(const unsigned*)(pa + 8 * ASTR + 8);
            }
#pragma unroll
            for (int ni = 0; ni < 4; ni++) {
                const __half* pb = sB + (wn + ni * 8 + lq) * ASTR + kk + lr * 2;
                b[ni][0] = *(const unsigned*)pb;
                b[ni][1] = *(const unsigned*)(pb + 8);
            }
#pragma unroll
            for (int mi = 0; mi < 2; mi++)
#pragma unroll
                for (int ni = 0; ni < 4; ni++)
                    mma_f16(acc[mi][ni], a[mi], b[ni]);
        }
        __syncthreads();
        if (t + 3 < ntiles) load_tile(t + 3, (t + 3) & (NSTAGE - 1));
        asm volatile("cp.async.commit_group;");
    }

    // Epilogue
    constexpr bool HAS_BIAS = (EPI == EPI_BIAS || EPI == EPI_BIAS_RES ||
                               EPI == EPI_BIAS_GELU || EPI == EPI_QKV);
    const bool vtile = (EPI == EPI_QKV) && (n0 >= 2048);
    float rp[2][2];
    if (EPI == EPI_EXP) {
#pragma unroll
        for (int i = 0; i < 2; i++) { rp[i][0] = 0.f; rp[i][1] = 0.f; }
    }
#pragma unroll
    for (int mi = 0; mi < 2; mi++) {
#pragma unroll
        for (int ni = 0; ni < 4; ni++) {
            const int row = m0 + wm + mi * 16 + lq;
            const int col = n0 + wn + ni * 8 + lr * 2;
            float bx = 0.f, by = 0.f;
            if (HAS_BIAS) { bx = bias[col]; by = bias[col + 1]; }
#pragma unroll
            for (int h = 0; h < 2; h++) {
                const int r = row + h * 8;
                float v0 = acc[mi][ni][h * 2 + 0] + bx;
                float v1 = acc[mi][ni][h * 2 + 1] + by;
                if (EPI == EPI_BIAS_RES) {
                    v0 += resid[(size_t)r * ldc + col];
                    v1 += resid[(size_t)r * ldc + col + 1];
                }
                if (EPI == EPI_BIAS_GELU) {
                    v0 = 0.5f * v0 * (1.0f + erff(v0 * 0.70710678118654752f));
                    v1 = 0.5f * v1 * (1.0f + erff(v1 * 0.70710678118654752f));
                }
                if (EPI == EPI_EXP) {
                    v0 = __expf(escale * v0);
                    v1 = __expf(escale * v1);
                    rp[mi][h] += v0 + v1;
                }
                if (EPI == EPI_DIVROW) {
                    const float inv = 1.0f / rsum[r];
                    v0 *= inv;
                    v1 *= inv;
                }
                if (EPI == EPI_QKV && vtile) {
                    // stage transposed: stage[n_local][m_local]
                    const int cl = wn + ni * 8 + lr * 2;
                    const int rl = wm + mi * 16 + lq + h * 8;
                    smem[cl * PADH + rl]       = __float2half_rn(v0);
                    smem[(cl + 1) * PADH + rl] = __float2half_rn(v1);
                } else if constexpr (sizeof(OutT) == 2) {
                    __half2 o = __floats2half2_rn(v0, v1);
                    *(__half2*)((__half*)C + (size_t)r * ldc + col) = o;
                } else {
                    float2 o; o.x = v0; o.y = v1;
                    *(float2*)((float*)C + (size_t)r * ldc + col) = o;
                }
            }
        }
    }

    // QKV V-tile: coalesced transposed store to vT
    if (EPI == EPI_QKV && vtile) {
        __syncthreads();
        const int bidx = m0 >> 11;              // batch
        const int hh = (n0 - 2048) >> 9;        // head
        const int vn0 = (n0 - 2048) & 511;
        const int mloc0 = m0 & 2047;
        __half* vbase = vTp + (long long)(bidx * 2 + hh) * (512LL * 2048);
#pragma unroll
        for (int it = 0; it < 4; it++) {
            const int idx = tid + it * 512;     // 0..2047
            const int n = idx >> 4;             // 0..127
            const int mc = idx & 15;
            uint4 val = *(const uint4*)&smem[n * PADH + mc * 8];
            *(uint4*)&vbase[(size_t)(vn0 + n) * 2048 + mloc0 + mc * 8] = val;
        }
    }

    // EXP: reduce row partials across the CTA and store per-(z, n-tile) sums.
    if (EPI == EPI_EXP) {
        float* srow = (float*)smem;   // [4 n-warp groups][128 rows]
#pragma unroll
        for (int mi = 0; mi < 2; mi++) {
#pragma unroll
            for (int h = 0; h < 2; h++) {
                float v = rp[mi][h];
                v += __shfl_xor_sync(0xffffffffu, v, 1);
                v += __shfl_xor_sync(0xffffffffu, v, 2);
                if (lr == 0)
                    srow[(warp >> 2) * 128 + wm + mi * 16 + lq + h * 8] = v;
            }
        }
        __syncthreads();
        if (tid < 128) {
            float s = srow[tid] + srow[128 + tid] + srow[256 + tid] + srow[384 + tid];
            parts[((long long)z * 16 + blockIdx.x) * 2048 + m0 + tid] = s;
        }
    }
}

// ---------------------------------------------------------------------------
// Final row-sum reduce: rowsum[z][row] = sum over 16 n-tiles (fixed order).
// ---------------------------------------------------------------------------
__global__ __launch_bounds__(256) void rowred_k(const float* __restrict__ parts,
                                                float* __restrict__ rowsum)
{
    const int idx = blockIdx.x * 256 + threadIdx.x;   // 0..32767
    const int z = idx >> 11;
    const int row = idx & 2047;
    const float* p = parts + (long long)z * 16 * 2048 + row;
    float s = 0.0f;
#pragma unroll
    for (int i = 0; i < 16; i++) s += p[i * 2048];
    rowsum[idx] = s;
}

// ---------------------------------------------------------------------------
// LayerNorm (C=1024): fp32 in -> fp16 out. One block per row.
// ---------------------------------------------------------------------------
__global__ __launch_bounds__(256) void ln_k(
    const float* __restrict__ x, const float* __restrict__ w,
    const float* __restrict__ b, __half* __restrict__ out)
{
    const size_t row = blockIdx.x;
    const int tid = threadIdx.x;
    float4 v = ((const float4*)(x + row * 1024))[tid];
    float sum = v.x + v.y + v.z + v.w;
    float sq = v.x * v.x + v.y * v.y + v.z * v.z + v.w * v.w;

    __shared__ float s1[8], s2[8];
#pragma unroll
    for (int o = 16; o; o >>= 1) {
        sum += __shfl_xor_sync(0xffffffffu, sum, o);
        sq  += __shfl_xor_sync(0xffffffffu, sq, o);
    }
    const int wid = tid >> 5, lid = tid & 31;
    if (!lid) { s1[wid] = sum; s2[wid] = sq; }
    __syncthreads();
    if (tid < 32) {
        float v1 = (tid < 8) ? s1[tid] : 0.0f;
        float v2 = (tid < 8) ? s2[tid] : 0.0f;
#pragma unroll
        for (int o = 4; o; o >>= 1) {
            v1 += __shfl_xor_sync(0xffffffffu, v1, o);
            v2 += __shfl_xor_sync(0xffffffffu, v2, o);
        }
        if (!tid) { s1[0] = v1; s2[0] = v2; }
    }
    __syncthreads();
    const float mu = s1[0] * (1.0f / 1024.0f);
    const float var = s2[0] * (1.0f / 1024.0f) - mu * mu;
    const float rstd = rsqrtf(var + 1e-5f);

    float4 w4 = ((const float4*)w)[tid];
    float4 b4 = ((const float4*)b)[tid];
    float o0 = (v.x - mu) * rstd * w4.x + b4.x;
    float o1 = (v.y - mu) * rstd * w4.y + b4.y;
    float o2 = (v.z - mu) * rstd * w4.z + b4.z;
    float o3 = (v.w - mu) * rstd * w4.w + b4.w;
    __half2* op = (__half2*)(out + row * 1024);
    op[tid * 2 + 0] = __floats2half2_rn(o0, o1);
    op[tid * 2 + 1] = __floats2half2_rn(o2, o3);
}

// ---------------------------------------------------------------------------
// All 4 weight transposes (fp32 [R][C] -> fp16 [C][R]) in one launch.
// ---------------------------------------------------------------------------
__global__ void wtrans_all(
    const float* __restrict__ qkv_w, const float* __restrict__ proj_w,
    const float* __restrict__ w1,    const float* __restrict__ w2,
    __half* __restrict__ qkvwT, __half* __restrict__ projwT,
    __half* __restrict__ w1T,   __half* __restrict__ w2T)
{
    __shared__ __half t[32][33];
    int b = blockIdx.x;
    const float* in; __half* out; int R, C, bid;
    if (b < 3072)      { in = qkv_w;  out = qkvwT;  R = 1024; C = 3072; bid = b; }
    else if (b < 4096) { in = proj_w; out = projwT; R = 1024; C = 1024; bid = b - 3072; }
    else if (b < 6144) { in = w1;     out = w1T;    R = 1024; C = 2048; bid = b - 4096; }
    else               { in = w2;     out = w2T;    R = 2048; C = 1024; bid = b - 6144; }
    const int cb = C / 32;
    const int c0 = (bid % cb) * 32, r0 = (bid / cb) * 32;
    const int x = threadIdx.x, y = threadIdx.y;
#pragma unroll
    for (int j = 0; j < 4; j++)
        t[y + j * 8][x] = __float2half_rn(in[(size_t)(r0 + y + j * 8) * C + c0 + x]);
    __syncthreads();
#pragma unroll
    for (int j = 0; j < 4; j++)
        out[(size_t)(c0 + y + j * 8) * R + r0 + x] = t[x][y + j * 8];
}

// ---------------------------------------------------------------------------
extern "C" void kernel_launch(void* const* d_in, const int* in_sizes, int n_in,
                              void* d_out, int out_size)
{
    const float* x      = (const float*)d_in[0];
    const float* ln1_w  = (const float*)d_in[1];
    const float* ln1_b  = (const float*)d_in[2];
    const float* qkv_w  = (const float*)d_in[3];
    const float* qkv_b  = (const float*)d_in[4];
    const float* proj_w = (const float*)d_in[5];
    const float* proj_b = (const float*)d_in[6];
    const float* ln2_w  = (const float*)d_in[7];
    const float* ln2_b  = (const float*)d_in[8];
    const float* mlp_w1 = (const float*)d_in[9];
    const float* mlp_b1 = (const float*)d_in[10];
    const float* mlp_w2 = (const float*)d_in[11];
    const float* mlp_b2 = (const float*)d_in[12];
    float* out = (float*)d_out;

    void *p;
    cudaGetSymbolAddress(&p, g_xn);       __half* xn      = (__half*)p;
    cudaGetSymbolAddress(&p, g_qkv);      __half* qkv     = (__half*)p;
    cudaGetSymbolAddress(&p, g_vT);       __half* vT      = (__half*)p;
    cudaGetSymbolAddress(&p, g_scores);   __half* scores  = (__half*)p;
    cudaGetSymbolAddress(&p, g_attnout);  __half* attnout = (__half*)p;
    cudaGetSymbolAddress(&p, g_x1);       float*  x1      = (float*)p;
    cudaGetSymbolAddress(&p, g_hdn);      __half* hdn     = (__half*)p;
    cudaGetSymbolAddress(&p, g_qkvwT);    __half* qkvwT   = (__half*)p;
    cudaGetSymbolAddress(&p, g_projwT);   __half* projwT  = (__half*)p;
    cudaGetSymbolAddress(&p, g_w1T);      __half* w1T     = (__half*)p;
    cudaGetSymbolAddress(&p, g_w2T);      __half* w2T     = (__half*)p;
    cudaGetSymbolAddress(&p, g_partials); float*  parts   = (float*)p;
    cudaGetSymbolAddress(&p, g_rowsum);   float*  rowsum  = (float*)p;

    cudaFuncSetAttribute(gemm_h<EPI_QKV, __half>,       cudaFuncAttributeMaxDynamicSharedMemorySize, SMEM_BYTES);
    cudaFuncSetAttribute(gemm_h<EPI_EXP, __half>,       cudaFuncAttributeMaxDynamicSharedMemorySize, SMEM_BYTES);
    cudaFuncSetAttribute(gemm_h<EPI_DIVROW, __half>,    cudaFuncAttributeMaxDynamicSharedMemorySize, SMEM_BYTES);
    cudaFuncSetAttribute(gemm_h<EPI_BIAS_RES, float>,   cudaFuncAttributeMaxDynamicSharedMemorySize, SMEM_BYTES);
    cudaFuncSetAttribute(gemm_h<EPI_BIAS_GELU, __half>, cudaFuncAttributeMaxDynamicSharedMemorySize, SMEM_BYTES);

    const int M = 16384;
    const long long X = 2048LL * 2048LL;
    dim3 tb(32, 8);

    // 0/1. Fork: weight transposes (s1) || LN1 (capture stream). Join before QKV.
    cudaStream_t s1;
    cudaStreamCreateWithFlags(&s1, cudaStreamNonBlocking);
    cudaEvent_t e0, e1;
    cudaEventCreateWithFlags(&e0, cudaEventDisableTiming);
    cudaEventCreateWithFlags(&e1, cudaEventDisableTiming);
    cudaEventRecord(e0, 0);
    cudaStreamWaitEvent(s1, e0, 0);
    wtrans_all<<<8192, tb, 0, s1>>>(qkv_w, proj_w, mlp_w1, mlp_w2,
                                    qkvwT, projwT, w1T, w2T);
    ln_k<<<M, 256>>>(x, ln1_w, ln1_b, xn);
    cudaEventRecord(e1, s1);
    cudaStreamWaitEvent(0, e1, 0);

    // 2. QKV: xn @ qkvwT^T + bias -> qkv (Q,K); V tiles transposed -> vT
    gemm_h<EPI_QKV, __half><<<dim3(3072 / BN, M / BM, 1), 512, SMEM_BYTES>>>(
        xn, qkvwT, qkv_b, nullptr, nullptr, nullptr, vT, 0.f, qkv,
        1024, 1024, 1024, 3072,
        0, 0, 0, 0, 0, 0, 1);

    // 3. Scores + fused exp + row partials -> scores (fp16), parts (fp32)
    gemm_h<EPI_EXP, __half><<<dim3(2048 / BN, 2048 / BM, 16), 512, SMEM_BYTES>>>(
        qkv, qkv + 1024, nullptr, nullptr, nullptr, parts, nullptr,
        0.04419417382415922f, scores,
        512, 3072, 3072, 2048,
        2048LL * 3072, 512,
        2048LL * 3072, 512,
        2 * X, X,
        2);

    // 4. Row-sum reduce (16 partials per row, fixed order)
    rowred_k<<<128, 256>>>(parts, rowsum);

    // 5. AV + normalize -> attnout (fp16)
    gemm_h<EPI_DIVROW, __half><<<dim3(512 / BN, 2048 / BM, 16), 512, SMEM_BYTES>>>(
        scores, vT, nullptr, nullptr, rowsum, nullptr, nullptr, 0.f, attnout,
        2048, 2048, 2048, 1024,
        2 * X, X,
        2048LL * 512 * 2, 512LL * 2048,
        2048LL * 1024, 512,
        2);

    // 6. Proj + residual(x) -> x1 (fp32)
    gemm_h<EPI_BIAS_RES, float><<<dim3(1024 / BN, M / BM, 1), 512, SMEM_BYTES>>>(
        attnout, projwT, proj_b, x, nullptr, nullptr, nullptr, 0.f, x1,
        1024, 1024, 1024, 1024,
        0, 0, 0, 0, 0, 0, 1);

    // 7. LN2: x1 -> xn (fp16)
    ln_k<<<M, 256>>>(x1, ln2_w, ln2_b, xn);

    // 8. MLP1 + GELU -> hdn (fp16)
    gemm_h<EPI_BIAS_GELU, __half><<<dim3(2048 / BN, M / BM, 1), 512, SMEM_BYTES>>>(
        xn, w1T, mlp_b1, nullptr, nullptr, nullptr, nullptr, 0.f, hdn,
        1024, 1024, 1024, 2048,
        0, 0, 0, 0, 0, 0, 1);

    // 9. MLP2 + residual(x1) -> out (fp32)
    gemm_h<EPI_BIAS_RES, float><<<dim3(1024 / BN, M / BM, 1), 512, SMEM_BYTES>>>(
        hdn, w2T, mlp_b2, x1, nullptr, nullptr, nullptr, 0.f, out,
        2048, 2048, 2048, 1024,
        0, 0, 0, 0, 0, 0, 1);

    cudaStreamDestroy(s1);
    cudaEventDestroy(e0);
    cudaEventDestroy(e1);
}

// round 15
// speedup vs baseline: 1.1049x; 1.1049x over previous
#include <cuda_runtime.h>
#include <cuda_fp16.h>
#include <math.h>

// ---------------------------------------------------------------------------
// B=8, N=2048, C=1024, heads=2, d=512, H=2048.  M = B*N = 16384.
// GEMMs: fp16 in (A[m][k], B[n][k]), fp32 accum, mma.sync m16n8k16,
// 4-stage cp.async, 128x128 CTA tiles / 256 threads / 64x32 warp tiles
// (empirical optimum: tensor-issue-rate limited; occupancy/barrier/depth/
// tile-shape probes all neutral-or-negative). Softmax fused into GEMM
// epilogues (exp + row partials; AV normalizes); V transpose fused into the
// QKV epilogue; weight transposes overlap LN1 on a forked capture stream.
// ---------------------------------------------------------------------------

#define BM 128
#define BN 128
#define BK 32
#define ASTR 40                        // padded smem row stride (80B)
#define NSTAGE 4
#define STG_HALFS (2 * 128 * ASTR)     // A + B per stage (20KB)
#define SMEM_BYTES (NSTAGE * STG_HALFS * 2)
#define PADH 136                       // V-transpose stage row stride (halfs)

enum { EPI_NONE = 0, EPI_BIAS = 1, EPI_BIAS_RES = 2, EPI_BIAS_GELU = 3,
       EPI_EXP = 4, EPI_DIVROW = 5, EPI_QKV = 6 };

// ---------------- scratch (device globals, allocation-free) ----------------
__device__ __half g_xn[16384 * 1024];
__device__ __half g_qkv[16384 * 3072];
__device__ __half g_vT[16ull * 512 * 2048];
__device__ __half g_scores[16ull * 2048 * 2048];
__device__ __half g_attnout[16384 * 1024];
__device__ float  g_x1[16384 * 1024];
__device__ __half g_hdn[16384 * 2048];
__device__ __half g_qkvwT[3072 * 1024];
__device__ __half g_projwT[1024 * 1024];
__device__ __half g_w1T[2048 * 1024];
__device__ __half g_w2T[1024 * 2048];
__device__ float  g_partials[16 * 16 * 2048];   // [z][ntile][row]
__device__ float  g_rowsum[16 * 2048];

__device__ __forceinline__ void cpa16(__half* dst, const __half* src) {
    unsigned d = (unsigned)__cvta_generic_to_shared(dst);
    asm volatile("cp.async.cg.shared.global [%0], [%1], 16;" :: "r"(d), "l"(src));
}

__device__ __forceinline__ void mma_f16(float c[4], const unsigned a[4], const unsigned b[2]) {
    asm volatile(
        "mma.sync.aligned.m16n8k16.row.col.f32.f16.f16.f32 "
        "{%0,%1,%2,%3}, {%4,%5,%6,%7}, {%8,%9}, {%0,%1,%2,%3};"
        : "+f"(c[0]), "+f"(c[1]), "+f"(c[2]), "+f"(c[3])
        : "r"(a[0]), "r"(a[1]), "r"(a[2]), "r"(a[3]), "r"(b[0]), "r"(b[1]));
}

// ---------------------------------------------------------------------------
// fp16 tensor-core GEMM: C[z] = A[z] @ B[z]^T + epilogue.
// A: [M][K] ld=lda, B: [N][K] ld=ldb. K % 32 == 0, K/32 >= 3.
// ---------------------------------------------------------------------------
template <int EPI, typename OutT>
__global__ __launch_bounds__(256, 2) void gemm_h(
    const __half* __restrict__ A, const __half* __restrict__ B,
    const float* __restrict__ bias, const float* __restrict__ resid,
    const float* __restrict__ rsum, float* __restrict__ parts,
    __half* __restrict__ vTp, float escale,
    OutT* __restrict__ C,
    int K, int lda, int ldb, int ldc,
    long long soA, long long siA,
    long long soB, long long siB,
    long long soC, long long siC, int ic)
{
    extern __shared__ __half smem[];

    const int z = blockIdx.z;
    A += (long long)(z / ic) * soA + (long long)(z % ic) * siA;
    B += (long long)(z / ic) * soB + (long long)(z % ic) * siB;
    C += (long long)(z / ic) * soC + (long long)(z % ic) * siC;
    if (EPI == EPI_DIVROW) rsum += (long long)z * 2048;

    const int m0 = blockIdx.y * BM;
    const int n0 = blockIdx.x * BN;
    const int tid = threadIdx.x;
    const int lane = tid & 31;
    const int warp = tid >> 5;
    const int wm = (warp & 1) * 64;
    const int wn = (warp >> 1) * 32;
    const int lq = lane >> 2;
    const int lr = lane & 3;

    float acc[4][4][4];
#pragma unroll
    for (int i = 0; i < 4; i++)
#pragma unroll
        for (int j = 0; j < 4; j++)
#pragma unroll
            for (int c = 0; c < 4; c++) acc[i][j][c] = 0.0f;

    const int ldr = tid >> 2;
    const int ldc4 = (tid & 3) * 8;

    auto load_tile = [&](int t, int s) {
        __half* sA = smem + s * STG_HALFS;
        __half* sB = sA + 128 * ASTR;
        const __half* gA = A + (size_t)(m0 + ldr) * lda + t * BK + ldc4;
        const __half* gB = B + (size_t)(n0 + ldr) * ldb + t * BK + ldc4;
        cpa16(sA + ldr * ASTR + ldc4, gA);
        cpa16(sA + (ldr + 64) * ASTR + ldc4, gA + (size_t)64 * lda);
        cpa16(sB + ldr * ASTR + ldc4, gB);
        cpa16(sB + (ldr + 64) * ASTR + ldc4, gB + (size_t)64 * ldb);
    };

    const int ntiles = K / BK;
    load_tile(0, 0);
    asm volatile("cp.async.commit_group;");
    load_tile(1, 1);
    asm volatile("cp.async.commit_group;");
    load_tile(2, 2);
    asm volatile("cp.async.commit_group;");

    for (int t = 0; t < ntiles; t++) {
        const int p = t & (NSTAGE - 1);
        asm volatile("cp.async.wait_group 2;");
        __syncthreads();

        const __half* sA = smem + p * STG_HALFS;
        const __half* sB = sA + 128 * ASTR;
#pragma unroll
        for (int kk = 0; kk < BK; kk += 16) {
            unsigned a[4][4], b[4][2];
#pragma unroll
            for (int mi = 0; mi < 4; mi++) {
                const __half* pa = sA + (wm + mi * 16 + lq) * ASTR + kk + lr * 2;
                a[mi][0] = *(const unsigned*)pa;
                a[mi][1] = *(const unsigned*)(pa + 8 * ASTR);
                a[mi][2] = *(const unsigned*)(pa + 8);
                a[mi][3] = *(const unsigned*)(pa + 8 * ASTR + 8);
            }
#pragma unroll
            for (int ni = 0; ni < 4; ni++) {
                const __half* pb = sB + (wn + ni * 8 + lq) * ASTR + kk + lr * 2;
                b[ni][0] = *(const unsigned*)pb;
                b[ni][1] = *(const unsigned*)(pb + 8);
            }
#pragma unroll
            for (int mi = 0; mi < 4; mi++)
#pragma unroll
                for (int ni = 0; ni < 4; ni++)
                    mma_f16(acc[mi][ni], a[mi], b[ni]);
        }
        __syncthreads();
        if (t + 3 < ntiles) load_tile(t + 3, (t + 3) & (NSTAGE - 1));
        asm volatile("cp.async.commit_group;");
    }

    // Epilogue
    constexpr bool HAS_BIAS = (EPI == EPI_BIAS || EPI == EPI_BIAS_RES ||
                               EPI == EPI_BIAS_GELU || EPI == EPI_QKV);
    const bool vtile = (EPI == EPI_QKV) && (n0 >= 2048);
    float rp[4][2];
    if (EPI == EPI_EXP) {
#pragma unroll
        for (int i = 0; i < 4; i++) { rp[i][0] = 0.f; rp[i][1] = 0.f; }
    }
#pragma unroll
    for (int mi = 0; mi < 4; mi++) {
#pragma unroll
        for (int ni = 0; ni < 4; ni++) {
            const int row = m0 + wm + mi * 16 + lq;
            const int col = n0 + wn + ni * 8 + lr * 2;
            float bx = 0.f, by = 0.f;
            if (HAS_BIAS) { bx = bias[col]; by = bias[col + 1]; }
#pragma unroll
            for (int h = 0; h < 2; h++) {
                const int r = row + h * 8;
                float v0 = acc[mi][ni][h * 2 + 0] + bx;
                float v1 = acc[mi][ni][h * 2 + 1] + by;
                if (EPI == EPI_BIAS_RES) {
                    v0 += resid[(size_t)r * ldc + col];
                    v1 += resid[(size_t)r * ldc + col + 1];
                }
                if (EPI == EPI_BIAS_GELU) {
                    v0 = 0.5f * v0 * (1.0f + erff(v0 * 0.70710678118654752f));
                    v1 = 0.5f * v1 * (1.0f + erff(v1 * 0.70710678118654752f));
                }
                if (EPI == EPI_EXP) {
                    v0 = __expf(escale * v0);
                    v1 = __expf(escale * v1);
                    rp[mi][h] += v0 + v1;
                }
                if (EPI == EPI_DIVROW) {
                    const float inv = 1.0f / rsum[r];
                    v0 *= inv;
                    v1 *= inv;
                }
                if (EPI == EPI_QKV && vtile) {
                    // stage transposed: stage[n_local][m_local]
                    const int cl = wn + ni * 8 + lr * 2;
                    const int rl = wm + mi * 16 + lq + h * 8;
                    smem[cl * PADH + rl]       = __float2half_rn(v0);
                    smem[(cl + 1) * PADH + rl] = __float2half_rn(v1);
                } else if constexpr (sizeof(OutT) == 2) {
                    __half2 o = __floats2half2_rn(v0, v1);
                    *(__half2*)((__half*)C + (size_t)r * ldc + col) = o;
                } else {
                    float2 o; o.x = v0; o.y = v1;
                    *(float2*)((float*)C + (size_t)r * ldc + col) = o;
                }
            }
        }
    }

    // QKV V-tile: coalesced transposed store to vT
    if (EPI == EPI_QKV && vtile) {
        __syncthreads();
        const int bidx = m0 >> 11;              // batch
        const int hh = (n0 - 2048) >> 9;        // head
        const int vn0 = (n0 - 2048) & 511;
        const int mloc0 = m0 & 2047;
        __half* vbase = vTp + (long long)(bidx * 2 + hh) * (512LL * 2048);
#pragma unroll
        for (int it = 0; it < 8; it++) {
            const int idx = tid + it * 256;
            const int n = idx >> 4;
            const int mc = idx & 15;
            uint4 val = *(const uint4*)&smem[n * PADH + mc * 8];
            *(uint4*)&vbase[(size_t)(vn0 + n) * 2048 + mloc0 + mc * 8] = val;
        }
    }

    // EXP: reduce row partials across the CTA and store per-(z, n-tile) sums.
    if (EPI == EPI_EXP) {
        float* srow = (float*)smem;   // [4 warp-cols][128 rows]
#pragma unroll
        for (int mi = 0; mi < 4; mi++) {
#pragma unroll
            for (int h = 0; h < 2; h++) {
                float v = rp[mi][h];
                v += __shfl_xor_sync(0xffffffffu, v, 1);
                v += __shfl_xor_sync(0xffffffffu, v, 2);
                if (lr == 0)
                    srow[(warp >> 1) * 128 + wm + mi * 16 + lq + h * 8] = v;
            }
        }
        __syncthreads();
        if (tid < 128) {
            float s = srow[tid] + srow[128 + tid] + srow[256 + tid] + srow[384 + tid];
            parts[((long long)z * 16 + blockIdx.x) * 2048 + m0 + tid] = s;
        }
    }
}

// ---------------------------------------------------------------------------
// Final row-sum reduce: rowsum[z][row] = sum over 16 n-tiles (fixed order).
// ---------------------------------------------------------------------------
__global__ __launch_bounds__(256) void rowred_k(const float* __restrict__ parts,
                                                float* __restrict__ rowsum)
{
    const int idx = blockIdx.x * 256 + threadIdx.x;   // 0..32767
    const int z = idx >> 11;
    const int row = idx & 2047;
    const float* p = parts + (long long)z * 16 * 2048 + row;
    float s = 0.0f;
#pragma unroll
    for (int i = 0; i < 16; i++) s += p[i * 2048];
    rowsum[idx] = s;
}

// ---------------------------------------------------------------------------
// LayerNorm (C=1024): fp32 in -> fp16 out. One block per row.
// ---------------------------------------------------------------------------
__global__ __launch_bounds__(256) void ln_k(
    const float* __restrict__ x, const float* __restrict__ w,
    const float* __restrict__ b, __half* __restrict__ out)
{
    const size_t row = blockIdx.x;
    const int tid = threadIdx.x;
    float4 v = ((const float4*)(x + row * 1024))[tid];
    float sum = v.x + v.y + v.z + v.w;
    float sq = v.x * v.x + v.y * v.y + v.z * v.z + v.w * v.w;

    __shared__ float s1[8], s2[8];
#pragma unroll
    for (int o = 16; o; o >>= 1) {
        sum += __shfl_xor_sync(0xffffffffu, sum, o);
        sq  += __shfl_xor_sync(0xffffffffu, sq, o);
    }
    const int wid = tid >> 5, lid = tid & 31;
    if (!lid) { s1[wid] = sum; s2[wid] = sq; }
    __syncthreads();
    if (tid < 32) {
        float v1 = (tid < 8) ? s1[tid] : 0.0f;
        float v2 = (tid < 8) ? s2[tid] : 0.0f;
#pragma unroll
        for (int o = 4; o; o >>= 1) {
            v1 += __shfl_xor_sync(0xffffffffu, v1, o);
            v2 += __shfl_xor_sync(0xffffffffu, v2, o);
        }
        if (!tid) { s1[0] = v1; s2[0] = v2; }
    }
    __syncthreads();
    const float mu = s1[0] * (1.0f / 1024.0f);
    const float var = s2[0] * (1.0f / 1024.0f) - mu * mu;
    const float rstd = rsqrtf(var + 1e-5f);

    float4 w4 = ((const float4*)w)[tid];
    float4 b4 = ((const float4*)b)[tid];
    float o0 = (v.x - mu) * rstd * w4.x + b4.x;
    float o1 = (v.y - mu) * rstd * w4.y + b4.y;
    float o2 = (v.z - mu) * rstd * w4.z + b4.z;
    float o3 = (v.w - mu) * rstd * w4.w + b4.w;
    __half2* op = (__half2*)(out + row * 1024);
    op[tid * 2 + 0] = __floats2half2_rn(o0, o1);
    op[tid * 2 + 1] = __floats2half2_rn(o2, o3);
}

// ---------------------------------------------------------------------------
// All 4 weight transposes (fp32 [R][C] -> fp16 [C][R]) in one launch.
// ---------------------------------------------------------------------------
__global__ void wtrans_all(
    const float* __restrict__ qkv_w, const float* __restrict__ proj_w,
    const float* __restrict__ w1,    const float* __restrict__ w2,
    __half* __restrict__ qkvwT, __half* __restrict__ projwT,
    __half* __restrict__ w1T,   __half* __restrict__ w2T)
{
    __shared__ __half t[32][33];
    int b = blockIdx.x;
    const float* in; __half* out; int R, C, bid;
    if (b < 3072)      { in = qkv_w;  out = qkvwT;  R = 1024; C = 3072; bid = b; }
    else if (b < 4096) { in = proj_w; out = projwT; R = 1024; C = 1024; bid = b - 3072; }
    else if (b < 6144) { in = w1;     out = w1T;    R = 1024; C = 2048; bid = b - 4096; }
    else               { in = w2;     out = w2T;    R = 2048; C = 1024; bid = b - 6144; }
    const int cb = C / 32;
    const int c0 = (bid % cb) * 32, r0 = (bid / cb) * 32;
    const int x = threadIdx.x, y = threadIdx.y;
#pragma unroll
    for (int j = 0; j < 4; j++)
        t[y + j * 8][x] = __float2half_rn(in[(size_t)(r0 + y + j * 8) * C + c0 + x]);
    __syncthreads();
#pragma unroll
    for (int j = 0; j < 4; j++)
        out[(size_t)(c0 + y + j * 8) * R + r0 + x] = t[x][y + j * 8];
}

// ---------------------------------------------------------------------------
extern "C" void kernel_launch(void* const* d_in, const int* in_sizes, int n_in,
                              void* d_out, int out_size)
{
    const float* x      = (const float*)d_in[0];
    const float* ln1_w  = (const float*)d_in[1];
    const float* ln1_b  = (const float*)d_in[2];
    const float* qkv_w  = (const float*)d_in[3];
    const float* qkv_b  = (const float*)d_in[4];
    const float* proj_w = (const float*)d_in[5];
    const float* proj_b = (const float*)d_in[6];
    const float* ln2_w  = (const float*)d_in[7];
    const float* ln2_b  = (const float*)d_in[8];
    const float* mlp_w1 = (const float*)d_in[9];
    const float* mlp_b1 = (const float*)d_in[10];
    const float* mlp_w2 = (const float*)d_in[11];
    const float* mlp_b2 = (const float*)d_in[12];
    float* out = (float*)d_out;

    void *p;
    cudaGetSymbolAddress(&p, g_xn);       __half* xn      = (__half*)p;
    cudaGetSymbolAddress(&p, g_qkv);      __half* qkv     = (__half*)p;
    cudaGetSymbolAddress(&p, g_vT);       __half* vT      = (__half*)p;
    cudaGetSymbolAddress(&p, g_scores);   __half* scores  = (__half*)p;
    cudaGetSymbolAddress(&p, g_attnout);  __half* attnout = (__half*)p;
    cudaGetSymbolAddress(&p, g_x1);       float*  x1      = (float*)p;
    cudaGetSymbolAddress(&p, g_hdn);      __half* hdn     = (__half*)p;
    cudaGetSymbolAddress(&p, g_qkvwT);    __half* qkvwT   = (__half*)p;
    cudaGetSymbolAddress(&p, g_projwT);   __half* projwT  = (__half*)p;
    cudaGetSymbolAddress(&p, g_w1T);      __half* w1T     = (__half*)p;
    cudaGetSymbolAddress(&p, g_w2T);      __half* w2T     = (__half*)p;
    cudaGetSymbolAddress(&p, g_partials); float*  parts   = (float*)p;
    cudaGetSymbolAddress(&p, g_rowsum);   float*  rowsum  = (float*)p;

    cudaFuncSetAttribute(gemm_h<EPI_QKV, __half>,       cudaFuncAttributeMaxDynamicSharedMemorySize, SMEM_BYTES);
    cudaFuncSetAttribute(gemm_h<EPI_EXP, __half>,       cudaFuncAttributeMaxDynamicSharedMemorySize, SMEM_BYTES);
    cudaFuncSetAttribute(gemm_h<EPI_DIVROW, __half>,    cudaFuncAttributeMaxDynamicSharedMemorySize, SMEM_BYTES);
    cudaFuncSetAttribute(gemm_h<EPI_BIAS_RES, float>,   cudaFuncAttributeMaxDynamicSharedMemorySize, SMEM_BYTES);
    cudaFuncSetAttribute(gemm_h<EPI_BIAS_GELU, __half>, cudaFuncAttributeMaxDynamicSharedMemorySize, SMEM_BYTES);

    const int M = 16384;
    const long long X = 2048LL * 2048LL;
    dim3 tb(32, 8);

    // 0/1. Fork: weight transposes (s1) || LN1 (capture stream). Join before QKV.
    cudaStream_t s1;
    cudaStreamCreateWithFlags(&s1, cudaStreamNonBlocking);
    cudaEvent_t e0, e1;
    cudaEventCreateWithFlags(&e0, cudaEventDisableTiming);
    cudaEventCreateWithFlags(&e1, cudaEventDisableTiming);
    cudaEventRecord(e0, 0);
    cudaStreamWaitEvent(s1, e0, 0);
    wtrans_all<<<8192, tb, 0, s1>>>(qkv_w, proj_w, mlp_w1, mlp_w2,
                                    qkvwT, projwT, w1T, w2T);
    ln_k<<<M, 256>>>(x, ln1_w, ln1_b, xn);
    cudaEventRecord(e1, s1);
    cudaStreamWaitEvent(0, e1, 0);

    // 2. QKV: xn @ qkvwT^T + bias -> qkv (Q,K); V tiles transposed -> vT
    gemm_h<EPI_QKV, __half><<<dim3(3072 / BN, M / BM, 1), 256, SMEM_BYTES>>>(
        xn, qkvwT, qkv_b, nullptr, nullptr, nullptr, vT, 0.f, qkv,
        1024, 1024, 1024, 3072,
        0, 0, 0, 0, 0, 0, 1);

    // 3. Scores + fused exp + row partials -> scores (fp16), parts (fp32)
    gemm_h<EPI_EXP, __half><<<dim3(2048 / BN, 2048 / BM, 16), 256, SMEM_BYTES>>>(
        qkv, qkv + 1024, nullptr, nullptr, nullptr, parts, nullptr,
        0.04419417382415922f, scores,
        512, 3072, 3072, 2048,
        2048LL * 3072, 512,
        2048LL * 3072, 512,
        2 * X, X,
        2);

    // 4. Row-sum reduce (16 partials per row, fixed order)
    rowred_k<<<128, 256>>>(parts, rowsum);

    // 5. AV + normalize -> attnout (fp16)
    gemm_h<EPI_DIVROW, __half><<<dim3(512 / BN, 2048 / BM, 16), 256, SMEM_BYTES>>>(
        scores, vT, nullptr, nullptr, rowsum, nullptr, nullptr, 0.f, attnout,
        2048, 2048, 2048, 1024,
        2 * X, X,
        2048LL * 512 * 2, 512LL * 2048,
        2048LL * 1024, 512,
        2);

    // 6. Proj + residual(x) -> x1 (fp32)
    gemm_h<EPI_BIAS_RES, float><<<dim3(1024 / BN, M / BM, 1), 256, SMEM_BYTES>>>(
        attnout, projwT, proj_b, x, nullptr, nullptr, nullptr, 0.f, x1,
        1024, 1024, 1024, 1024,
        0, 0, 0, 0, 0, 0, 1);

    // 7. LN2: x1 -> xn (fp16)
    ln_k<<<M, 256>>>(x1, ln2_w, ln2_b, xn);

    // 8. MLP1 + GELU -> hdn (fp16)
    gemm_h<EPI_BIAS_GELU, __half><<<dim3(2048 / BN, M / BM, 1), 256, SMEM_BYTES>>>(
        xn, w1T, mlp_b1, nullptr, nullptr, nullptr, nullptr, 0.f, hdn,
        1024, 1024, 1024, 2048,
        0, 0, 0, 0, 0, 0, 1);

    // 9. MLP2 + residual(x1) -> out (fp32)
    gemm_h<EPI_BIAS_RES, float><<<dim3(1024 / BN, M / BM, 1), 256, SMEM_BYTES>>>(
        hdn, w2T, mlp_b2, x1, nullptr, nullptr, nullptr, 0.f, out,
        2048, 2048, 2048, 1024,
        0, 0, 0, 0, 0, 0, 1);

    cudaStreamDestroy(s1);
    cudaEventDestroy(e0);
    cudaEventDestroy(e1);
}

// round 16
// speedup vs baseline: 1.1127x; 1.0071x over previous
#include <cuda_runtime.h>
#include <cuda_fp16.h>
#include <math.h>

// ---------------------------------------------------------------------------
// B=8, N=2048, C=1024, heads=2, d=512, H=2048.  M = B*N = 16384.
// GEMMs: fp16 in (A[m][k], B[n][k]), mma.sync m16n8k16, 4-stage cp.async,
// 128x128 CTA tiles / 256 threads / 64x32 warp tiles (empirical optimum).
// Accumulation: fp32 everywhere EXCEPT the scores GEMM (EPI_EXP), which uses
// fp16 accumulate (K=512, well-conditioned) to probe the 2x HMMA rate.
// Softmax fused into GEMM epilogues; V transpose fused into QKV epilogue;
// weight transposes overlap LN1 on a forked capture stream.
// ---------------------------------------------------------------------------

#define BM 128
#define BN 128
#define BK 32
#define ASTR 40                        // padded smem row stride (80B)
#define NSTAGE 4
#define STG_HALFS (2 * 128 * ASTR)     // A + B per stage (20KB)
#define SMEM_BYTES (NSTAGE * STG_HALFS * 2)
#define PADH 136                       // V-transpose stage row stride (halfs)

enum { EPI_NONE = 0, EPI_BIAS = 1, EPI_BIAS_RES = 2, EPI_BIAS_GELU = 3,
       EPI_EXP = 4, EPI_DIVROW = 5, EPI_QKV = 6 };

// ---------------- scratch (device globals, allocation-free) ----------------
__device__ __half g_xn[16384 * 1024];
__device__ __half g_qkv[16384 * 3072];
__device__ __half g_vT[16ull * 512 * 2048];
__device__ __half g_scores[16ull * 2048 * 2048];
__device__ __half g_attnout[16384 * 1024];
__device__ float  g_x1[16384 * 1024];
__device__ __half g_hdn[16384 * 2048];
__device__ __half g_qkvwT[3072 * 1024];
__device__ __half g_projwT[1024 * 1024];
__device__ __half g_w1T[2048 * 1024];
__device__ __half g_w2T[1024 * 2048];
__device__ float  g_partials[16 * 16 * 2048];   // [z][ntile][row]
__device__ float  g_rowsum[16 * 2048];

__device__ __forceinline__ void cpa16(__half* dst, const __half* src) {
    unsigned d = (unsigned)__cvta_generic_to_shared(dst);
    asm volatile("cp.async.cg.shared.global [%0], [%1], 16;" :: "r"(d), "l"(src));
}

__device__ __forceinline__ void mma_f16(float c[4], const unsigned a[4], const unsigned b[2]) {
    asm volatile(
        "mma.sync.aligned.m16n8k16.row.col.f32.f16.f16.f32 "
        "{%0,%1,%2,%3}, {%4,%5,%6,%7}, {%8,%9}, {%0,%1,%2,%3};"
        : "+f"(c[0]), "+f"(c[1]), "+f"(c[2]), "+f"(c[3])
        : "r"(a[0]), "r"(a[1]), "r"(a[2]), "r"(a[3]), "r"(b[0]), "r"(b[1]));
}

__device__ __forceinline__ void mma_f16acc(unsigned c[2], const unsigned a[4], const unsigned b[2]) {
    asm volatile(
        "mma.sync.aligned.m16n8k16.row.col.f16.f16.f16.f16 "
        "{%0,%1}, {%2,%3,%4,%5}, {%6,%7}, {%0,%1};"
        : "+r"(c[0]), "+r"(c[1])
        : "r"(a[0]), "r"(a[1]), "r"(a[2]), "r"(a[3]), "r"(b[0]), "r"(b[1]));
}

// ---------------------------------------------------------------------------
// fp16 tensor-core GEMM: C[z] = A[z] @ B[z]^T + epilogue.
// A: [M][K] ld=lda, B: [N][K] ld=ldb. K % 32 == 0, K/32 >= 3.
// EPI_EXP uses fp16 accumulation (safe at K=512 with ~N(0,1) inputs).
// ---------------------------------------------------------------------------
template <int EPI, typename OutT>
__global__ __launch_bounds__(256, 2) void gemm_h(
    const __half* __restrict__ A, const __half* __restrict__ B,
    const float* __restrict__ bias, const float* __restrict__ resid,
    const float* __restrict__ rsum, float* __restrict__ parts,
    __half* __restrict__ vTp, float escale,
    OutT* __restrict__ C,
    int K, int lda, int ldb, int ldc,
    long long soA, long long siA,
    long long soB, long long siB,
    long long soC, long long siC, int ic)
{
    extern __shared__ __half smem[];
    constexpr bool F16ACC = (EPI == EPI_EXP);

    const int z = blockIdx.z;
    A += (long long)(z / ic) * soA + (long long)(z % ic) * siA;
    B += (long long)(z / ic) * soB + (long long)(z % ic) * siB;
    C += (long long)(z / ic) * soC + (long long)(z % ic) * siC;
    if (EPI == EPI_DIVROW) rsum += (long long)z * 2048;

    const int m0 = blockIdx.y * BM;
    const int n0 = blockIdx.x * BN;
    const int tid = threadIdx.x;
    const int lane = tid & 31;
    const int warp = tid >> 5;
    const int wm = (warp & 1) * 64;
    const int wn = (warp >> 1) * 32;
    const int lq = lane >> 2;
    const int lr = lane & 3;

    float accf[F16ACC ? 1 : 4][4][4];
    unsigned acch[F16ACC ? 4 : 1][4][2];
    if constexpr (F16ACC) {
#pragma unroll
        for (int i = 0; i < 4; i++)
#pragma unroll
            for (int j = 0; j < 4; j++) { acch[i][j][0] = 0u; acch[i][j][1] = 0u; }
    } else {
#pragma unroll
        for (int i = 0; i < 4; i++)
#pragma unroll
            for (int j = 0; j < 4; j++)
#pragma unroll
                for (int c = 0; c < 4; c++) accf[i][j][c] = 0.0f;
    }

    const int ldr = tid >> 2;
    const int ldc4 = (tid & 3) * 8;

    auto load_tile = [&](int t, int s) {
        __half* sA = smem + s * STG_HALFS;
        __half* sB = sA + 128 * ASTR;
        const __half* gA = A + (size_t)(m0 + ldr) * lda + t * BK + ldc4;
        const __half* gB = B + (size_t)(n0 + ldr) * ldb + t * BK + ldc4;
        cpa16(sA + ldr * ASTR + ldc4, gA);
        cpa16(sA + (ldr + 64) * ASTR + ldc4, gA + (size_t)64 * lda);
        cpa16(sB + ldr * ASTR + ldc4, gB);
        cpa16(sB + (ldr + 64) * ASTR + ldc4, gB + (size_t)64 * ldb);
    };

    const int ntiles = K / BK;
    load_tile(0, 0);
    asm volatile("cp.async.commit_group;");
    load_tile(1, 1);
    asm volatile("cp.async.commit_group;");
    load_tile(2, 2);
    asm volatile("cp.async.commit_group;");

    for (int t = 0; t < ntiles; t++) {
        const int p = t & (NSTAGE - 1);
        asm volatile("cp.async.wait_group 2;");
        __syncthreads();

        const __half* sA = smem + p * STG_HALFS;
        const __half* sB = sA + 128 * ASTR;
#pragma unroll
        for (int kk = 0; kk < BK; kk += 16) {
            unsigned a[4][4], b[4][2];
#pragma unroll
            for (int mi = 0; mi < 4; mi++) {
                const __half* pa = sA + (wm + mi * 16 + lq) * ASTR + kk + lr * 2;
                a[mi][0] = *(const unsigned*)pa;
                a[mi][1] = *(const unsigned*)(pa + 8 * ASTR);
                a[mi][2] = *(const unsigned*)(pa + 8);
                a[mi][3] = *(const unsigned*)(pa + 8 * ASTR + 8);
            }
#pragma unroll
            for (int ni = 0; ni < 4; ni++) {
                const __half* pb = sB + (wn + ni * 8 + lq) * ASTR + kk + lr * 2;
                b[ni][0] = *(const unsigned*)pb;
                b[ni][1] = *(const unsigned*)(pb + 8);
            }
#pragma unroll
            for (int mi = 0; mi < 4; mi++)
#pragma unroll
                for (int ni = 0; ni < 4; ni++) {
                    if constexpr (F16ACC)
                        mma_f16acc(acch[mi][ni], a[mi], b[ni]);
                    else
                        mma_f16(accf[mi][ni], a[mi], b[ni]);
                }
        }
        __syncthreads();
        if (t + 3 < ntiles) load_tile(t + 3, (t + 3) & (NSTAGE - 1));
        asm volatile("cp.async.commit_group;");
    }

    // Epilogue
    constexpr bool HAS_BIAS = (EPI == EPI_BIAS || EPI == EPI_BIAS_RES ||
                               EPI == EPI_BIAS_GELU || EPI == EPI_QKV);
    const bool vtile = (EPI == EPI_QKV) && (n0 >= 2048);
    float rp[4][2];
    if (EPI == EPI_EXP) {
#pragma unroll
        for (int i = 0; i < 4; i++) { rp[i][0] = 0.f; rp[i][1] = 0.f; }
    }
#pragma unroll
    for (int mi = 0; mi < 4; mi++) {
#pragma unroll
        for (int ni = 0; ni < 4; ni++) {
            const int row = m0 + wm + mi * 16 + lq;
            const int col = n0 + wn + ni * 8 + lr * 2;
            float bx = 0.f, by = 0.f;
            if (HAS_BIAS) { bx = bias[col]; by = bias[col + 1]; }
#pragma unroll
            for (int h = 0; h < 2; h++) {
                const int r = row + h * 8;
                float v0, v1;
                if constexpr (F16ACC) {
                    __half2 hv = *(__half2*)&acch[mi][ni][h];
                    v0 = __low2float(hv);
                    v1 = __high2float(hv);
                } else {
                    v0 = accf[mi][ni][h * 2 + 0] + bx;
                    v1 = accf[mi][ni][h * 2 + 1] + by;
                }
                if (EPI == EPI_BIAS_RES) {
                    v0 += resid[(size_t)r * ldc + col];
                    v1 += resid[(size_t)r * ldc + col + 1];
                }
                if (EPI == EPI_BIAS_GELU) {
                    v0 = 0.5f * v0 * (1.0f + erff(v0 * 0.70710678118654752f));
                    v1 = 0.5f * v1 * (1.0f + erff(v1 * 0.70710678118654752f));
                }
                if (EPI == EPI_EXP) {
                    v0 = __expf(escale * v0);
                    v1 = __expf(escale * v1);
                    rp[mi][h] += v0 + v1;
                }
                if (EPI == EPI_DIVROW) {
                    const float inv = 1.0f / rsum[r];
                    v0 *= inv;
                    v1 *= inv;
                }
                if (EPI == EPI_QKV && vtile) {
                    // stage transposed: stage[n_local][m_local]
                    const int cl = wn + ni * 8 + lr * 2;
                    const int rl = wm + mi * 16 + lq + h * 8;
                    smem[cl * PADH + rl]       = __float2half_rn(v0);
                    smem[(cl + 1) * PADH + rl] = __float2half_rn(v1);
                } else if constexpr (sizeof(OutT) == 2) {
                    __half2 o = __floats2half2_rn(v0, v1);
                    *(__half2*)((__half*)C + (size_t)r * ldc + col) = o;
                } else {
                    float2 o; o.x = v0; o.y = v1;
                    *(float2*)((float*)C + (size_t)r * ldc + col) = o;
                }
            }
        }
    }

    // QKV V-tile: coalesced transposed store to vT
    if (EPI == EPI_QKV && vtile) {
        __syncthreads();
        const int bidx = m0 >> 11;              // batch
        const int hh = (n0 - 2048) >> 9;        // head
        const int vn0 = (n0 - 2048) & 511;
        const int mloc0 = m0 & 2047;
        __half* vbase = vTp + (long long)(bidx * 2 + hh) * (512LL * 2048);
#pragma unroll
        for (int it = 0; it < 8; it++) {
            const int idx = tid + it * 256;
            const int n = idx >> 4;
            const int mc = idx & 15;
            uint4 val = *(const uint4*)&smem[n * PADH + mc * 8];
            *(uint4*)&vbase[(size_t)(vn0 + n) * 2048 + mloc0 + mc * 8] = val;
        }
    }

    // EXP: reduce row partials across the CTA and store per-(z, n-tile) sums.
    if (EPI == EPI_EXP) {
        float* srow = (float*)smem;   // [4 warp-cols][128 rows]
#pragma unroll
        for (int mi = 0; mi < 4; mi++) {
#pragma unroll
            for (int h = 0; h < 2; h++) {
                float v = rp[mi][h];
                v += __shfl_xor_sync(0xffffffffu, v, 1);
                v += __shfl_xor_sync(0xffffffffu, v, 2);
                if (lr == 0)
                    srow[(warp >> 1) * 128 + wm + mi * 16 + lq + h * 8] = v;
            }
        }
        __syncthreads();
        if (tid < 128) {
            float s = srow[tid] + srow[128 + tid] + srow[256 + tid] + srow[384 + tid];
            parts[((long long)z * 16 + blockIdx.x) * 2048 + m0 + tid] = s;
        }
    }
}

// ---------------------------------------------------------------------------
// Final row-sum reduce: rowsum[z][row] = sum over 16 n-tiles (fixed order).
// ---------------------------------------------------------------------------
__global__ __launch_bounds__(256) void rowred_k(const float* __restrict__ parts,
                                                float* __restrict__ rowsum)
{
    const int idx = blockIdx.x * 256 + threadIdx.x;   // 0..32767
    const int z = idx >> 11;
    const int row = idx & 2047;
    const float* p = parts + (long long)z * 16 * 2048 + row;
    float s = 0.0f;
#pragma unroll
    for (int i = 0; i < 16; i++) s += p[i * 2048];
    rowsum[idx] = s;
}

// ---------------------------------------------------------------------------
// LayerNorm (C=1024): fp32 in -> fp16 out. One block per row.
// ---------------------------------------------------------------------------
__global__ __launch_bounds__(256) void ln_k(
    const float* __restrict__ x, const float* __restrict__ w,
    const float* __restrict__ b, __half* __restrict__ out)
{
    const size_t row = blockIdx.x;
    const int tid = threadIdx.x;
    float4 v = ((const float4*)(x + row * 1024))[tid];
    float sum = v.x + v.y + v.z + v.w;
    float sq = v.x * v.x + v.y * v.y + v.z * v.z + v.w * v.w;

    __shared__ float s1[8], s2[8];
#pragma unroll
    for (int o = 16; o; o >>= 1) {
        sum += __shfl_xor_sync(0xffffffffu, sum, o);
        sq  += __shfl_xor_sync(0xffffffffu, sq, o);
    }
    const int wid = tid >> 5, lid = tid & 31;
    if (!lid) { s1[wid] = sum; s2[wid] = sq; }
    __syncthreads();
    if (tid < 32) {
        float v1 = (tid < 8) ? s1[tid] : 0.0f;
        float v2 = (tid < 8) ? s2[tid] : 0.0f;
#pragma unroll
        for (int o = 4; o; o >>= 1) {
            v1 += __shfl_xor_sync(0xffffffffu, v1, o);
            v2 += __shfl_xor_sync(0xffffffffu, v2, o);
        }
        if (!tid) { s1[0] = v1; s2[0] = v2; }
    }
    __syncthreads();
    const float mu = s1[0] * (1.0f / 1024.0f);
    const float var = s2[0] * (1.0f / 1024.0f) - mu * mu;
    const float rstd = rsqrtf(var + 1e-5f);

    float4 w4 = ((const float4*)w)[tid];
    float4 b4 = ((const float4*)b)[tid];
    float o0 = (v.x - mu) * rstd * w4.x + b4.x;
    float o1 = (v.y - mu) * rstd * w4.y + b4.y;
    float o2 = (v.z - mu) * rstd * w4.z + b4.z;
    float o3 = (v.w - mu) * rstd * w4.w + b4.w;
    __half2* op = (__half2*)(out + row * 1024);
    op[tid * 2 + 0] = __floats2half2_rn(o0, o1);
    op[tid * 2 + 1] = __floats2half2_rn(o2, o3);
}

// ---------------------------------------------------------------------------
// All 4 weight transposes (fp32 [R][C] -> fp16 [C][R]) in one launch.
// ---------------------------------------------------------------------------
__global__ void wtrans_all(
    const float* __restrict__ qkv_w, const float* __restrict__ proj_w,
    const float* __restrict__ w1,    const float* __restrict__ w2,
    __half* __restrict__ qkvwT, __half* __restrict__ projwT,
    __half* __restrict__ w1T,   __half* __restrict__ w2T)
{
    __shared__ __half t[32][33];
    int b = blockIdx.x;
    const float* in; __half* out; int R, C, bid;
    if (b < 3072)      { in = qkv_w;  out = qkvwT;  R = 1024; C = 3072; bid = b; }
    else if (b < 4096) { in = proj_w; out = projwT; R = 1024; C = 1024; bid = b - 3072; }
    else if (b < 6144) { in = w1;     out = w1T;    R = 1024; C = 2048; bid = b - 4096; }
    else               { in = w2;     out = w2T;    R = 2048; C = 1024; bid = b - 6144; }
    const int cb = C / 32;
    const int c0 = (bid % cb) * 32, r0 = (bid / cb) * 32;
    const int x = threadIdx.x, y = threadIdx.y;
#pragma unroll
    for (int j = 0; j < 4; j++)
        t[y + j * 8][x] = __float2half_rn(in[(size_t)(r0 + y + j * 8) * C + c0 + x]);
    __syncthreads();
#pragma unroll
    for (int j = 0; j < 4; j++)
        out[(size_t)(c0 + y + j * 8) * R + r0 + x] = t[x][y + j * 8];
}

// ---------------------------------------------------------------------------
extern "C" void kernel_launch(void* const* d_in, const int* in_sizes, int n_in,
                              void* d_out, int out_size)
{
    const float* x      = (const float*)d_in[0];
    const float* ln1_w  = (const float*)d_in[1];
    const float* ln1_b  = (const float*)d_in[2];
    const float* qkv_w  = (const float*)d_in[3];
    const float* qkv_b  = (const float*)d_in[4];
    const float* proj_w = (const float*)d_in[5];
    const float* proj_b = (const float*)d_in[6];
    const float* ln2_w  = (const float*)d_in[7];
    const float* ln2_b  = (const float*)d_in[8];
    const float* mlp_w1 = (const float*)d_in[9];
    const float* mlp_b1 = (const float*)d_in[10];
    const float* mlp_w2 = (const float*)d_in[11];
    const float* mlp_b2 = (const float*)d_in[12];
    float* out = (float*)d_out;

    void *p;
    cudaGetSymbolAddress(&p, g_xn);       __half* xn      = (__half*)p;
    cudaGetSymbolAddress(&p, g_qkv);      __half* qkv     = (__half*)p;
    cudaGetSymbolAddress(&p, g_vT);       __half* vT      = (__half*)p;
    cudaGetSymbolAddress(&p, g_scores);   __half* scores  = (__half*)p;
    cudaGetSymbolAddress(&p, g_attnout);  __half* attnout = (__half*)p;
    cudaGetSymbolAddress(&p, g_x1);       float*  x1      = (float*)p;
    cudaGetSymbolAddress(&p, g_hdn);      __half* hdn     = (__half*)p;
    cudaGetSymbolAddress(&p, g_qkvwT);    __half* qkvwT   = (__half*)p;
    cudaGetSymbolAddress(&p, g_projwT);   __half* projwT  = (__half*)p;
    cudaGetSymbolAddress(&p, g_w1T);      __half* w1T     = (__half*)p;
    cudaGetSymbolAddress(&p, g_w2T);      __half* w2T     = (__half*)p;
    cudaGetSymbolAddress(&p, g_partials); float*  parts   = (float*)p;
    cudaGetSymbolAddress(&p, g_rowsum);   float*  rowsum  = (float*)p;

    cudaFuncSetAttribute(gemm_h<EPI_QKV, __half>,       cudaFuncAttributeMaxDynamicSharedMemorySize, SMEM_BYTES);
    cudaFuncSetAttribute(gemm_h<EPI_EXP, __half>,       cudaFuncAttributeMaxDynamicSharedMemorySize, SMEM_BYTES);
    cudaFuncSetAttribute(gemm_h<EPI_DIVROW, __half>,    cudaFuncAttributeMaxDynamicSharedMemorySize, SMEM_BYTES);
    cudaFuncSetAttribute(gemm_h<EPI_BIAS_RES, float>,   cudaFuncAttributeMaxDynamicSharedMemorySize, SMEM_BYTES);
    cudaFuncSetAttribute(gemm_h<EPI_BIAS_GELU, __half>, cudaFuncAttributeMaxDynamicSharedMemorySize, SMEM_BYTES);

    const int M = 16384;
    const long long X = 2048LL * 2048LL;
    dim3 tb(32, 8);

    // 0/1. Fork: weight transposes (s1) || LN1 (capture stream). Join before QKV.
    cudaStream_t s1;
    cudaStreamCreateWithFlags(&s1, cudaStreamNonBlocking);
    cudaEvent_t e0, e1;
    cudaEventCreateWithFlags(&e0, cudaEventDisableTiming);
    cudaEventCreateWithFlags(&e1, cudaEventDisableTiming);
    cudaEventRecord(e0, 0);
    cudaStreamWaitEvent(s1, e0, 0);
    wtrans_all<<<8192, tb, 0, s1>>>(qkv_w, proj_w, mlp_w1, mlp_w2,
                                    qkvwT, projwT, w1T, w2T);
    ln_k<<<M, 256>>>(x, ln1_w, ln1_b, xn);
    cudaEventRecord(e1, s1);
    cudaStreamWaitEvent(0, e1, 0);

    // 2. QKV: xn @ qkvwT^T + bias -> qkv (Q,K); V tiles transposed -> vT
    gemm_h<EPI_QKV, __half><<<dim3(3072 / BN, M / BM, 1), 256, SMEM_BYTES>>>(
        xn, qkvwT, qkv_b, nullptr, nullptr, nullptr, vT, 0.f, qkv,
        1024, 1024, 1024, 3072,
        0, 0, 0, 0, 0, 0, 1);

    // 3. Scores + fused exp + row partials (fp16 accumulate) -> scores, parts
    gemm_h<EPI_EXP, __half><<<dim3(2048 / BN, 2048 / BM, 16), 256, SMEM_BYTES>>>(
        qkv, qkv + 1024, nullptr, nullptr, nullptr, parts, nullptr,
        0.04419417382415922f, scores,
        512, 3072, 3072, 2048,
        2048LL * 3072, 512,
        2048LL * 3072, 512,
        2 * X, X,
        2);

    // 4. Row-sum reduce (16 partials per row, fixed order)
    rowred_k<<<128, 256>>>(parts, rowsum);

    // 5. AV + normalize -> attnout (fp16, fp32 accumulate)
    gemm_h<EPI_DIVROW, __half><<<dim3(512 / BN, 2048 / BM, 16), 256, SMEM_BYTES>>>(
        scores, vT, nullptr, nullptr, rowsum, nullptr, nullptr, 0.f, attnout,
        2048, 2048, 2048, 1024,
        2 * X, X,
        2048LL * 512 * 2, 512LL * 2048,
        2048LL * 1024, 512,
        2);

    // 6. Proj + residual(x) -> x1 (fp32)
    gemm_h<EPI_BIAS_RES, float><<<dim3(1024 / BN, M / BM, 1), 256, SMEM_BYTES>>>(
        attnout, projwT, proj_b, x, nullptr, nullptr, nullptr, 0.f, x1,
        1024, 1024, 1024, 1024,
        0, 0, 0, 0, 0, 0, 1);

    // 7. LN2: x1 -> xn (fp16)
    ln_k<<<M, 256>>>(x1, ln2_w, ln2_b, xn);

    // 8. MLP1 + GELU -> hdn (fp16)
    gemm_h<EPI_BIAS_GELU, __half><<<dim3(2048 / BN, M / BM, 1), 256, SMEM_BYTES>>>(
        xn, w1T, mlp_b1, nullptr, nullptr, nullptr, nullptr, 0.f, hdn,
        1024, 1024, 1024, 2048,
        0, 0, 0, 0, 0, 0, 1);

    // 9. MLP2 + residual(x1) -> out (fp32)
    gemm_h<EPI_BIAS_RES, float><<<dim3(1024 / BN, M / BM, 1), 256, SMEM_BYTES>>>(
        hdn, w2T, mlp_b2, x1, nullptr, nullptr, nullptr, 0.f, out,
        2048, 2048, 2048, 1024,
        0, 0, 0, 0, 0, 0, 1);

    cudaStreamDestroy(s1);
    cudaEventDestroy(e0);
    cudaEventDestroy(e1);
}

// round 17
// speedup vs baseline: 1.1349x; 1.0199x over previous
#include <cuda_runtime.h>
#include <cuda_fp16.h>
#include <math.h>

// ---------------------------------------------------------------------------
// B=8, N=2048, C=1024, heads=2, d=512, H=2048.  M = B*N = 16384.
// GEMMs: fp16 in (A[m][k], B[n][k]), mma.sync m16n8k16, 4-stage cp.async,
// 128x128 CTA tiles / 256 threads / 64x32 warp tiles.
// Accumulation: fp16 for scores/AV/QKV (numerically safe, ~4%/launch faster
// via shorter acc chains + reg relief); fp32 for proj/MLP (error path
// undiluted there). Softmax fused into GEMM epilogues; V transpose fused
// into QKV epilogue; weight transposes overlap LN1 on a forked stream.
// ---------------------------------------------------------------------------

#define BM 128
#define BN 128
#define BK 32
#define ASTR 40                        // padded smem row stride (80B)
#define NSTAGE 4
#define STG_HALFS (2 * 128 * ASTR)     // A + B per stage (20KB)
#define SMEM_BYTES (NSTAGE * STG_HALFS * 2)
#define PADH 136                       // V-transpose stage row stride (halfs)

enum { EPI_NONE = 0, EPI_BIAS = 1, EPI_BIAS_RES = 2, EPI_BIAS_GELU = 3,
       EPI_EXP = 4, EPI_DIVROW = 5, EPI_QKV = 6 };

// ---------------- scratch (device globals, allocation-free) ----------------
__device__ __half g_xn[16384 * 1024];
__device__ __half g_qkv[16384 * 3072];
__device__ __half g_vT[16ull * 512 * 2048];
__device__ __half g_scores[16ull * 2048 * 2048];
__device__ __half g_attnout[16384 * 1024];
__device__ float  g_x1[16384 * 1024];
__device__ __half g_hdn[16384 * 2048];
__device__ __half g_qkvwT[3072 * 1024];
__device__ __half g_projwT[1024 * 1024];
__device__ __half g_w1T[2048 * 1024];
__device__ __half g_w2T[1024 * 2048];
__device__ float  g_partials[16 * 16 * 2048];   // [z][ntile][row]
__device__ float  g_rowsum[16 * 2048];

__device__ __forceinline__ void cpa16(__half* dst, const __half* src) {
    unsigned d = (unsigned)__cvta_generic_to_shared(dst);
    asm volatile("cp.async.cg.shared.global [%0], [%1], 16;" :: "r"(d), "l"(src));
}

__device__ __forceinline__ void mma_f16(float c[4], const unsigned a[4], const unsigned b[2]) {
    asm volatile(
        "mma.sync.aligned.m16n8k16.row.col.f32.f16.f16.f32 "
        "{%0,%1,%2,%3}, {%4,%5,%6,%7}, {%8,%9}, {%0,%1,%2,%3};"
        : "+f"(c[0]), "+f"(c[1]), "+f"(c[2]), "+f"(c[3])
        : "r"(a[0]), "r"(a[1]), "r"(a[2]), "r"(a[3]), "r"(b[0]), "r"(b[1]));
}

__device__ __forceinline__ void mma_f16acc(unsigned c[2], const unsigned a[4], const unsigned b[2]) {
    asm volatile(
        "mma.sync.aligned.m16n8k16.row.col.f16.f16.f16.f16 "
        "{%0,%1}, {%2,%3,%4,%5}, {%6,%7}, {%0,%1};"
        : "+r"(c[0]), "+r"(c[1])
        : "r"(a[0]), "r"(a[1]), "r"(a[2]), "r"(a[3]), "r"(b[0]), "r"(b[1]));
}

// ---------------------------------------------------------------------------
// fp16 tensor-core GEMM: C[z] = A[z] @ B[z]^T + epilogue.
// A: [M][K] ld=lda, B: [N][K] ld=ldb. K % 32 == 0, K/32 >= 3.
// fp16 accumulate for EXP / DIVROW / QKV; fp32 otherwise.
// ---------------------------------------------------------------------------
template <int EPI, typename OutT>
__global__ __launch_bounds__(256, 2) void gemm_h(
    const __half* __restrict__ A, const __half* __restrict__ B,
    const float* __restrict__ bias, const float* __restrict__ resid,
    const float* __restrict__ rsum, float* __restrict__ parts,
    __half* __restrict__ vTp, float escale,
    OutT* __restrict__ C,
    int K, int lda, int ldb, int ldc,
    long long soA, long long siA,
    long long soB, long long siB,
    long long soC, long long siC, int ic)
{
    extern __shared__ __half smem[];
    constexpr bool F16ACC = (EPI == EPI_EXP || EPI == EPI_DIVROW || EPI == EPI_QKV);

    const int z = blockIdx.z;
    A += (long long)(z / ic) * soA + (long long)(z % ic) * siA;
    B += (long long)(z / ic) * soB + (long long)(z % ic) * siB;
    C += (long long)(z / ic) * soC + (long long)(z % ic) * siC;
    if (EPI == EPI_DIVROW) rsum += (long long)z * 2048;

    const int m0 = blockIdx.y * BM;
    const int n0 = blockIdx.x * BN;
    const int tid = threadIdx.x;
    const int lane = tid & 31;
    const int warp = tid >> 5;
    const int wm = (warp & 1) * 64;
    const int wn = (warp >> 1) * 32;
    const int lq = lane >> 2;
    const int lr = lane & 3;

    float accf[F16ACC ? 1 : 4][4][4];
    unsigned acch[F16ACC ? 4 : 1][4][2];
    if constexpr (F16ACC) {
#pragma unroll
        for (int i = 0; i < 4; i++)
#pragma unroll
            for (int j = 0; j < 4; j++) { acch[i][j][0] = 0u; acch[i][j][1] = 0u; }
    } else {
#pragma unroll
        for (int i = 0; i < 4; i++)
#pragma unroll
            for (int j = 0; j < 4; j++)
#pragma unroll
                for (int c = 0; c < 4; c++) accf[i][j][c] = 0.0f;
    }

    const int ldr = tid >> 2;
    const int ldc4 = (tid & 3) * 8;

    auto load_tile = [&](int t, int s) {
        __half* sA = smem + s * STG_HALFS;
        __half* sB = sA + 128 * ASTR;
        const __half* gA = A + (size_t)(m0 + ldr) * lda + t * BK + ldc4;
        const __half* gB = B + (size_t)(n0 + ldr) * ldb + t * BK + ldc4;
        cpa16(sA + ldr * ASTR + ldc4, gA);
        cpa16(sA + (ldr + 64) * ASTR + ldc4, gA + (size_t)64 * lda);
        cpa16(sB + ldr * ASTR + ldc4, gB);
        cpa16(sB + (ldr + 64) * ASTR + ldc4, gB + (size_t)64 * ldb);
    };

    const int ntiles = K / BK;
    load_tile(0, 0);
    asm volatile("cp.async.commit_group;");
    load_tile(1, 1);
    asm volatile("cp.async.commit_group;");
    load_tile(2, 2);
    asm volatile("cp.async.commit_group;");

    for (int t = 0; t < ntiles; t++) {
        const int p = t & (NSTAGE - 1);
        asm volatile("cp.async.wait_group 2;");
        __syncthreads();

        const __half* sA = smem + p * STG_HALFS;
        const __half* sB = sA + 128 * ASTR;
#pragma unroll
        for (int kk = 0; kk < BK; kk += 16) {
            unsigned a[4][4], b[4][2];
#pragma unroll
            for (int mi = 0; mi < 4; mi++) {
                const __half* pa = sA + (wm + mi * 16 + lq) * ASTR + kk + lr * 2;
                a[mi][0] = *(const unsigned*)pa;
                a[mi][1] = *(const unsigned*)(pa + 8 * ASTR);
                a[mi][2] = *(const unsigned*)(pa + 8);
                a[mi][3] = *(const unsigned*)(pa + 8 * ASTR + 8);
            }
#pragma unroll
            for (int ni = 0; ni < 4; ni++) {
                const __half* pb = sB + (wn + ni * 8 + lq) * ASTR + kk + lr * 2;
                b[ni][0] = *(const unsigned*)pb;
                b[ni][1] = *(const unsigned*)(pb + 8);
            }
#pragma unroll
            for (int mi = 0; mi < 4; mi++)
#pragma unroll
                for (int ni = 0; ni < 4; ni++) {
                    if constexpr (F16ACC)
                        mma_f16acc(acch[mi][ni], a[mi], b[ni]);
                    else
                        mma_f16(accf[mi][ni], a[mi], b[ni]);
                }
        }
        __syncthreads();
        if (t + 3 < ntiles) load_tile(t + 3, (t + 3) & (NSTAGE - 1));
        asm volatile("cp.async.commit_group;");
    }

    // Epilogue (bias/resid/exp/div applied uniformly after unpack)
    constexpr bool HAS_BIAS = (EPI == EPI_BIAS || EPI == EPI_BIAS_RES ||
                               EPI == EPI_BIAS_GELU || EPI == EPI_QKV);
    const bool vtile = (EPI == EPI_QKV) && (n0 >= 2048);
    float rp[4][2];
    if (EPI == EPI_EXP) {
#pragma unroll
        for (int i = 0; i < 4; i++) { rp[i][0] = 0.f; rp[i][1] = 0.f; }
    }
#pragma unroll
    for (int mi = 0; mi < 4; mi++) {
#pragma unroll
        for (int ni = 0; ni < 4; ni++) {
            const int row = m0 + wm + mi * 16 + lq;
            const int col = n0 + wn + ni * 8 + lr * 2;
            float bx = 0.f, by = 0.f;
            if (HAS_BIAS) { bx = bias[col]; by = bias[col + 1]; }
#pragma unroll
            for (int h = 0; h < 2; h++) {
                const int r = row + h * 8;
                float v0, v1;
                if constexpr (F16ACC) {
                    __half2 hv = *(__half2*)&acch[mi][ni][h];
                    v0 = __low2float(hv);
                    v1 = __high2float(hv);
                } else {
                    v0 = accf[mi][ni][h * 2 + 0];
                    v1 = accf[mi][ni][h * 2 + 1];
                }
                if (HAS_BIAS) { v0 += bx; v1 += by; }
                if (EPI == EPI_BIAS_RES) {
                    v0 += resid[(size_t)r * ldc + col];
                    v1 += resid[(size_t)r * ldc + col + 1];
                }
                if (EPI == EPI_BIAS_GELU) {
                    v0 = 0.5f * v0 * (1.0f + erff(v0 * 0.70710678118654752f));
                    v1 = 0.5f * v1 * (1.0f + erff(v1 * 0.70710678118654752f));
                }
                if (EPI == EPI_EXP) {
                    v0 = __expf(escale * v0);
                    v1 = __expf(escale * v1);
                    rp[mi][h] += v0 + v1;
                }
                if (EPI == EPI_DIVROW) {
                    const float inv = 1.0f / rsum[r];
                    v0 *= inv;
                    v1 *= inv;
                }
                if (EPI == EPI_QKV && vtile) {
                    // stage transposed: stage[n_local][m_local]
                    const int cl = wn + ni * 8 + lr * 2;
                    const int rl = wm + mi * 16 + lq + h * 8;
                    smem[cl * PADH + rl]       = __float2half_rn(v0);
                    smem[(cl + 1) * PADH + rl] = __float2half_rn(v1);
                } else if constexpr (sizeof(OutT) == 2) {
                    __half2 o = __floats2half2_rn(v0, v1);
                    *(__half2*)((__half*)C + (size_t)r * ldc + col) = o;
                } else {
                    float2 o; o.x = v0; o.y = v1;
                    *(float2*)((float*)C + (size_t)r * ldc + col) = o;
                }
            }
        }
    }

    // QKV V-tile: coalesced transposed store to vT
    if (EPI == EPI_QKV && vtile) {
        __syncthreads();
        const int bidx = m0 >> 11;              // batch
        const int hh = (n0 - 2048) >> 9;        // head
        const int vn0 = (n0 - 2048) & 511;
        const int mloc0 = m0 & 2047;
        __half* vbase = vTp + (long long)(bidx * 2 + hh) * (512LL * 2048);
#pragma unroll
        for (int it = 0; it < 8; it++) {
            const int idx = tid + it * 256;
            const int n = idx >> 4;
            const int mc = idx & 15;
            uint4 val = *(const uint4*)&smem[n * PADH + mc * 8];
            *(uint4*)&vbase[(size_t)(vn0 + n) * 2048 + mloc0 + mc * 8] = val;
        }
    }

    // EXP: reduce row partials across the CTA and store per-(z, n-tile) sums.
    if (EPI == EPI_EXP) {
        float* srow = (float*)smem;   // [4 warp-cols][128 rows]
#pragma unroll
        for (int mi = 0; mi < 4; mi++) {
#pragma unroll
            for (int h = 0; h < 2; h++) {
                float v = rp[mi][h];
                v += __shfl_xor_sync(0xffffffffu, v, 1);
                v += __shfl_xor_sync(0xffffffffu, v, 2);
                if (lr == 0)
                    srow[(warp >> 1) * 128 + wm + mi * 16 + lq + h * 8] = v;
            }
        }
        __syncthreads();
        if (tid < 128) {
            float s = srow[tid] + srow[128 + tid] + srow[256 + tid] + srow[384 + tid];
            parts[((long long)z * 16 + blockIdx.x) * 2048 + m0 + tid] = s;
        }
    }
}

// ---------------------------------------------------------------------------
// Final row-sum reduce: rowsum[z][row] = sum over 16 n-tiles (fixed order).
// ---------------------------------------------------------------------------
__global__ __launch_bounds__(256) void rowred_k(const float* __restrict__ parts,
                                                float* __restrict__ rowsum)
{
    const int idx = blockIdx.x * 256 + threadIdx.x;   // 0..32767
    const int z = idx >> 11;
    const int row = idx & 2047;
    const float* p = parts + (long long)z * 16 * 2048 + row;
    float s = 0.0f;
#pragma unroll
    for (int i = 0; i < 16; i++) s += p[i * 2048];
    rowsum[idx] = s;
}

// ---------------------------------------------------------------------------
// LayerNorm (C=1024): fp32 in -> fp16 out. One block per row.
// ---------------------------------------------------------------------------
__global__ __launch_bounds__(256) void ln_k(
    const float* __restrict__ x, const float* __restrict__ w,
    const float* __restrict__ b, __half* __restrict__ out)
{
    const size_t row = blockIdx.x;
    const int tid = threadIdx.x;
    float4 v = ((const float4*)(x + row * 1024))[tid];
    float sum = v.x + v.y + v.z + v.w;
    float sq = v.x * v.x + v.y * v.y + v.z * v.z + v.w * v.w;

    __shared__ float s1[8], s2[8];
#pragma unroll
    for (int o = 16; o; o >>= 1) {
        sum += __shfl_xor_sync(0xffffffffu, sum, o);
        sq  += __shfl_xor_sync(0xffffffffu, sq, o);
    }
    const int wid = tid >> 5, lid = tid & 31;
    if (!lid) { s1[wid] = sum; s2[wid] = sq; }
    __syncthreads();
    if (tid < 32) {
        float v1 = (tid < 8) ? s1[tid] : 0.0f;
        float v2 = (tid < 8) ? s2[tid] : 0.0f;
#pragma unroll
        for (int o = 4; o; o >>= 1) {
            v1 += __shfl_xor_sync(0xffffffffu, v1, o);
            v2 += __shfl_xor_sync(0xffffffffu, v2, o);
        }
        if (!tid) { s1[0] = v1; s2[0] = v2; }
    }
    __syncthreads();
    const float mu = s1[0] * (1.0f / 1024.0f);
    const float var = s2[0] * (1.0f / 1024.0f) - mu * mu;
    const float rstd = rsqrtf(var + 1e-5f);

    float4 w4 = ((const float4*)w)[tid];
    float4 b4 = ((const float4*)b)[tid];
    float o0 = (v.x - mu) * rstd * w4.x + b4.x;
    float o1 = (v.y - mu) * rstd * w4.y + b4.y;
    float o2 = (v.z - mu) * rstd * w4.z + b4.z;
    float o3 = (v.w - mu) * rstd * w4.w + b4.w;
    __half2* op = (__half2*)(out + row * 1024);
    op[tid * 2 + 0] = __floats2half2_rn(o0, o1);
    op[tid * 2 + 1] = __floats2half2_rn(o2, o3);
}

// ---------------------------------------------------------------------------
// All 4 weight transposes (fp32 [R][C] -> fp16 [C][R]) in one launch.
// ---------------------------------------------------------------------------
__global__ void wtrans_all(
    const float* __restrict__ qkv_w, const float* __restrict__ proj_w,
    const float* __restrict__ w1,    const float* __restrict__ w2,
    __half* __restrict__ qkvwT, __half* __restrict__ projwT,
    __half* __restrict__ w1T,   __half* __restrict__ w2T)
{
    __shared__ __half t[32][33];
    int b = blockIdx.x;
    const float* in; __half* out; int R, C, bid;
    if (b < 3072)      { in = qkv_w;  out = qkvwT;  R = 1024; C = 3072; bid = b; }
    else if (b < 4096) { in = proj_w; out = projwT; R = 1024; C = 1024; bid = b - 3072; }
    else if (b < 6144) { in = w1;     out = w1T;    R = 1024; C = 2048; bid = b - 4096; }
    else               { in = w2;     out = w2T;    R = 2048; C = 1024; bid = b - 6144; }
    const int cb = C / 32;
    const int c0 = (bid % cb) * 32, r0 = (bid / cb) * 32;
    const int x = threadIdx.x, y = threadIdx.y;
#pragma unroll
    for (int j = 0; j < 4; j++)
        t[y + j * 8][x] = __float2half_rn(in[(size_t)(r0 + y + j * 8) * C + c0 + x]);
    __syncthreads();
#pragma unroll
    for (int j = 0; j < 4; j++)
        out[(size_t)(c0 + y + j * 8) * R + r0 + x] = t[x][y + j * 8];
}

// ---------------------------------------------------------------------------
extern "C" void kernel_launch(void* const* d_in, const int* in_sizes, int n_in,
                              void* d_out, int out_size)
{
    const float* x      = (const float*)d_in[0];
    const float* ln1_w  = (const float*)d_in[1];
    const float* ln1_b  = (const float*)d_in[2];
    const float* qkv_w  = (const float*)d_in[3];
    const float* qkv_b  = (const float*)d_in[4];
    const float* proj_w = (const float*)d_in[5];
    const float* proj_b = (const float*)d_in[6];
    const float* ln2_w  = (const float*)d_in[7];
    const float* ln2_b  = (const float*)d_in[8];
    const float* mlp_w1 = (const float*)d_in[9];
    const float* mlp_b1 = (const float*)d_in[10];
    const float* mlp_w2 = (const float*)d_in[11];
    const float* mlp_b2 = (const float*)d_in[12];
    float* out = (float*)d_out;

    void *p;
    cudaGetSymbolAddress(&p, g_xn);       __half* xn      = (__half*)p;
    cudaGetSymbolAddress(&p, g_qkv);      __half* qkv     = (__half*)p;
    cudaGetSymbolAddress(&p, g_vT);       __half* vT      = (__half*)p;
    cudaGetSymbolAddress(&p, g_scores);   __half* scores  = (__half*)p;
    cudaGetSymbolAddress(&p, g_attnout);  __half* attnout = (__half*)p;
    cudaGetSymbolAddress(&p, g_x1);       float*  x1      = (float*)p;
    cudaGetSymbolAddress(&p, g_hdn);      __half* hdn     = (__half*)p;
    cudaGetSymbolAddress(&p, g_qkvwT);    __half* qkvwT   = (__half*)p;
    cudaGetSymbolAddress(&p, g_projwT);   __half* projwT  = (__half*)p;
    cudaGetSymbolAddress(&p, g_w1T);      __half* w1T     = (__half*)p;
    cudaGetSymbolAddress(&p, g_w2T);      __half* w2T     = (__half*)p;
    cudaGetSymbolAddress(&p, g_partials); float*  parts   = (float*)p;
    cudaGetSymbolAddress(&p, g_rowsum);   float*  rowsum  = (float*)p;

    cudaFuncSetAttribute(gemm_h<EPI_QKV, __half>,       cudaFuncAttributeMaxDynamicSharedMemorySize, SMEM_BYTES);
    cudaFuncSetAttribute(gemm_h<EPI_EXP, __half>,       cudaFuncAttributeMaxDynamicSharedMemorySize, SMEM_BYTES);
    cudaFuncSetAttribute(gemm_h<EPI_DIVROW, __half>,    cudaFuncAttributeMaxDynamicSharedMemorySize, SMEM_BYTES);
    cudaFuncSetAttribute(gemm_h<EPI_BIAS_RES, float>,   cudaFuncAttributeMaxDynamicSharedMemorySize, SMEM_BYTES);
    cudaFuncSetAttribute(gemm_h<EPI_BIAS_GELU, __half>, cudaFuncAttributeMaxDynamicSharedMemorySize, SMEM_BYTES);

    const int M = 16384;
    const long long X = 2048LL * 2048LL;
    dim3 tb(32, 8);

    // 0/1. Fork: weight transposes (s1) || LN1 (capture stream). Join before QKV.
    cudaStream_t s1;
    cudaStreamCreateWithFlags(&s1, cudaStreamNonBlocking);
    cudaEvent_t e0, e1;
    cudaEventCreateWithFlags(&e0, cudaEventDisableTiming);
    cudaEventCreateWithFlags(&e1, cudaEventDisableTiming);
    cudaEventRecord(e0, 0);
    cudaStreamWaitEvent(s1, e0, 0);
    wtrans_all<<<8192, tb, 0, s1>>>(qkv_w, proj_w, mlp_w1, mlp_w2,
                                    qkvwT, projwT, w1T, w2T);
    ln_k<<<M, 256>>>(x, ln1_w, ln1_b, xn);
    cudaEventRecord(e1, s1);
    cudaStreamWaitEvent(0, e1, 0);

    // 2. QKV (fp16 acc): xn @ qkvwT^T + bias -> qkv (Q,K); V transposed -> vT
    gemm_h<EPI_QKV, __half><<<dim3(3072 / BN, M / BM, 1), 256, SMEM_BYTES>>>(
        xn, qkvwT, qkv_b, nullptr, nullptr, nullptr, vT, 0.f, qkv,
        1024, 1024, 1024, 3072,
        0, 0, 0, 0, 0, 0, 1);

    // 3. Scores + fused exp + row partials (fp16 acc) -> scores, parts
    gemm_h<EPI_EXP, __half><<<dim3(2048 / BN, 2048 / BM, 16), 256, SMEM_BYTES>>>(
        qkv, qkv + 1024, nullptr, nullptr, nullptr, parts, nullptr,
        0.04419417382415922f, scores,
        512, 3072, 3072, 2048,
        2048LL * 3072, 512,
        2048LL * 3072, 512,
        2 * X, X,
        2);

    // 4. Row-sum reduce (16 partials per row, fixed order)
    rowred_k<<<128, 256>>>(parts, rowsum);

    // 5. AV + normalize (fp16 acc) -> attnout (fp16)
    gemm_h<EPI_DIVROW, __half><<<dim3(512 / BN, 2048 / BM, 16), 256, SMEM_BYTES>>>(
        scores, vT, nullptr, nullptr, rowsum, nullptr, nullptr, 0.f, attnout,
        2048, 2048, 2048, 1024,
        2 * X, X,
        2048LL * 512 * 2, 512LL * 2048,
        2048LL * 1024, 512,
        2);

    // 6. Proj + residual(x) -> x1 (fp32 acc)
    gemm_h<EPI_BIAS_RES, float><<<dim3(1024 / BN, M / BM, 1), 256, SMEM_BYTES>>>(
        attnout, projwT, proj_b, x, nullptr, nullptr, nullptr, 0.f, x1,
        1024, 1024, 1024, 1024,
        0, 0, 0, 0, 0, 0, 1);

    // 7. LN2: x1 -> xn (fp16)
    ln_k<<<M, 256>>>(x1, ln2_w, ln2_b, xn);

    // 8. MLP1 + GELU -> hdn (fp32 acc)
    gemm_h<EPI_BIAS_GELU, __half><<<dim3(2048 / BN, M / BM, 1), 256, SMEM_BYTES>>>(
        xn, w1T, mlp_b1, nullptr, nullptr, nullptr, nullptr, 0.f, hdn,
        1024, 1024, 1024, 2048,
        0, 0, 0, 0, 0, 0, 1);

    // 9. MLP2 + residual(x1) -> out (fp32 acc)
    gemm_h<EPI_BIAS_RES, float><<<dim3(1024 / BN, M / BM, 1), 256, SMEM_BYTES>>>(
        hdn, w2T, mlp_b2, x1, nullptr, nullptr, nullptr, 0.f, out,
        2048, 2048, 2048, 1024,
        0, 0, 0, 0, 0, 0, 1);

    cudaStreamDestroy(s1);
    cudaEventDestroy(e0);
    cudaEventDestroy(e1);
}